// round 7
// baseline (speedup 1.0000x reference)
#include <cuda_runtime.h>
#include <cstdint>

// out[b, i*D+d, 0, t] = sum_c x[b,i,c,t] * renorm(w)[i*D+d, c]
#define B_ 32
#define I_ 16
#define C_ 128
#define T_ 2048
#define D_ 8
#define DEPTH 8   // cp.async pipeline depth (power of 2)

__device__ __forceinline__ unsigned long long pack2(float lo, float hi) {
    unsigned long long r;
    asm("mov.b64 %0, {%1, %2};" : "=l"(r) : "f"(lo), "f"(hi));
    return r;
}
__device__ __forceinline__ void unpack2(unsigned long long v, float& lo, float& hi) {
    asm("mov.b64 {%0, %1}, %2;" : "=f"(lo), "=f"(hi) : "l"(v));
}
// Packed dual-fp32 FMA (Blackwell FFMA2, PTX-only).
__device__ __forceinline__ unsigned long long fma2(unsigned long long a,
                                                   unsigned long long b,
                                                   unsigned long long c) {
    unsigned long long d;
    asm("fma.rn.f32x2 %0, %1, %2, %3;" : "=l"(d) : "l"(a), "l"(b), "l"(c));
    return d;
}

__device__ __forceinline__ void cp_async16(uint32_t saddr, const float* gaddr) {
    asm volatile("cp.async.cg.shared.global [%0], [%1], 16;"
                 :: "r"(saddr), "l"(gaddr));
}
__device__ __forceinline__ void cp_commit() {
    asm volatile("cp.async.commit_group;" ::: "memory");
}
template <int N>
__device__ __forceinline__ void cp_wait() {
    asm volatile("cp.async.wait_group %0;" :: "n"(N) : "memory");
}

// ---------------------------------------------------------------------------
// Fused kernel. Block = one (b, i, t-chunk of 1024); thread owns 4
// consecutive t. x streamed through an 8-deep thread-private cp.async ring.
// Weights renormed in-block during warmup shadow, stored transposed [c][d]
// as (w,w) u64 pairs; inner loop reads them as broadcast LDS.64 consumed
// immediately (minimal transient registers).
// __launch_bounds__(256, 5) squeezes regs to ~48 -> 5 blocks/SM, 40 warps.
// ---------------------------------------------------------------------------
__global__ __launch_bounds__(256, 5) void dwconv_kernel(
    const float* __restrict__ x,
    const float* __restrict__ w,
    float* __restrict__ out)
{
    __shared__ __align__(16) float4 xs[DEPTH][256];              // 32 KB ring
    __shared__ __align__(16) unsigned long long ws2t[C_ * D_];   // 8 KB, [c][d]

    const int tid = threadIdx.x;
    const int bid = blockIdx.x;
    const int tchunk = bid & 1;
    const int i      = (bid >> 1) & (I_ - 1);
    const int b      = bid >> 5;

    const int t0 = tchunk * 1024 + tid * 4;
    const float* xg = x + (size_t)(b * I_ + i) * C_ * T_ + t0;

    const uint32_t xs_base =
        (uint32_t)__cvta_generic_to_shared(&xs[0][0]) + (uint32_t)tid * 16u;

    // Kick off the pipeline before anything else touches memory.
    #pragma unroll
    for (int s = 0; s < DEPTH; s++) {
        cp_async16(xs_base + (uint32_t)s * (256u * 16u), xg + (size_t)s * T_);
        cp_commit();
    }

    // Renorm this i's weights in-block (hidden under warmup load latency).
    // Warp wid owns row d = wid; writes transposed duplicated pairs.
    {
        const int wid = tid >> 5, lane = tid & 31;
        const float* wr = w + (i * D_ + wid) * C_;
        float v0 = wr[lane], v1 = wr[lane + 32],
              v2 = wr[lane + 64], v3 = wr[lane + 96];
        float s = v0 * v0 + v1 * v1 + v2 * v2 + v3 * v3;
        #pragma unroll
        for (int off = 16; off > 0; off >>= 1)
            s += __shfl_xor_sync(0xffffffffu, s, off);
        float n = sqrtf(s);
        float sc = (n > 1.0f) ? (1.0f / n) : 1.0f;
        v0 *= sc; v1 *= sc; v2 *= sc; v3 *= sc;
        ws2t[(lane      ) * D_ + wid] = pack2(v0, v0);
        ws2t[(lane + 32 ) * D_ + wid] = pack2(v1, v1);
        ws2t[(lane + 64 ) * D_ + wid] = pack2(v2, v2);
        ws2t[(lane + 96 ) * D_ + wid] = pack2(v3, v3);
    }
    __syncthreads();

    unsigned long long acc01[D_], acc23[D_];
    #pragma unroll
    for (int d = 0; d < D_; d++) { acc01[d] = 0ull; acc23[d] = 0ull; }

    const float* xg_pf = xg + (size_t)DEPTH * T_;   // prefetch pointer base

    #pragma unroll 8
    for (int c = 0; c < C_; c++) {
        cp_wait<DEPTH - 1>();   // oldest group (stage c) landed

        float4 xv = xs[c & (DEPTH - 1)][tid];
        unsigned long long x01 = pack2(xv.x, xv.y);
        unsigned long long x23 = pack2(xv.z, xv.w);

        #pragma unroll
        for (int d = 0; d < D_; d++) {
            unsigned long long wv = ws2t[c * D_ + d];  // broadcast LDS.64
            acc01[d] = fma2(x01, wv, acc01[d]);
            acc23[d] = fma2(x23, wv, acc23[d]);
        }

        // Refill the slot just consumed (thread-private: no barrier needed).
        if (c < C_ - DEPTH)
            cp_async16(xs_base + (uint32_t)(c & (DEPTH - 1)) * (256u * 16u),
                       xg_pf + (size_t)c * T_);
        cp_commit();   // commit every iter (possibly empty) to keep accounting
    }

    float4* __restrict__ op = reinterpret_cast<float4*>(
        out + (size_t)(b * (I_ * D_) + i * D_) * T_ + t0);
    #pragma unroll
    for (int d = 0; d < D_; d++) {
        float4 o;
        unpack2(acc01[d], o.x, o.y);
        unpack2(acc23[d], o.z, o.w);
        op[(size_t)d * (T_ / 4)] = o;
    }
}

extern "C" void kernel_launch(void* const* d_in, const int* in_sizes, int n_in,
                              void* d_out, int out_size) {
    const float* x = (const float*)d_in[0];   // (32,16,128,2048) fp32
    const float* w = (const float*)d_in[1];   // (256,1,128,1)    fp32
    float* out = (float*)d_out;               // (32,256,1,2048)  fp32
    (void)in_sizes; (void)n_in; (void)out_size;

    dwconv_kernel<<<B_ * I_ * (T_ / 1024), 256>>>(x, w, out);
}

// round 8
// speedup vs baseline: 1.1281x; 1.1281x over previous
#include <cuda_runtime.h>
#include <cstdint>

// out[b, i*D+d, 0, t] = sum_c x[b,i,c,t] * renorm(w)[i*D+d, c]
#define B_ 32
#define I_ 16
#define C_ 128
#define T_ 2048
#define D_ 8
#define DEPTH 8     // cp.async pipeline depth (power of 2)
#define NT 128      // threads per block; each thread owns 8 consecutive t

__device__ __forceinline__ unsigned long long pack2(float lo, float hi) {
    unsigned long long r;
    asm("mov.b64 %0, {%1, %2};" : "=l"(r) : "f"(lo), "f"(hi));
    return r;
}
__device__ __forceinline__ void unpack2(unsigned long long v, float& lo, float& hi) {
    asm("mov.b64 {%0, %1}, %2;" : "=f"(lo), "=f"(hi) : "l"(v));
}
// Packed dual-fp32 FMA (Blackwell FFMA2, PTX-only).
__device__ __forceinline__ unsigned long long fma2(unsigned long long a,
                                                   unsigned long long b,
                                                   unsigned long long c) {
    unsigned long long d;
    asm("fma.rn.f32x2 %0, %1, %2, %3;" : "=l"(d) : "l"(a), "l"(b), "l"(c));
    return d;
}

__device__ __forceinline__ void cp_async16(uint32_t saddr, const float* gaddr) {
    asm volatile("cp.async.cg.shared.global [%0], [%1], 16;"
                 :: "r"(saddr), "l"(gaddr));
}
__device__ __forceinline__ void cp_commit() {
    asm volatile("cp.async.commit_group;" ::: "memory");
}
template <int N>
__device__ __forceinline__ void cp_wait() {
    asm volatile("cp.async.wait_group %0;" :: "n"(N) : "memory");
}

// ---------------------------------------------------------------------------
// Block = one (b, i, t-chunk of 1024). 128 threads, each owning 8 consecutive
// t (32 bytes -> two cp.async16 per stage). Weight LDS is amortized over 2x
// the FMAs vs the 4t/thread shape: 24 smem wavefronts per warp per c for 256
// elements (0.094 wf/elem) instead of 16 for 128 (0.125) -> smem port work
// drops below the DRAM floor. 5 blocks/SM (launch_bounds 128,5; <=102 regs).
// ---------------------------------------------------------------------------
__global__ __launch_bounds__(NT, 5) void dwconv_kernel(
    const float* __restrict__ x,
    const float* __restrict__ w,
    float* __restrict__ out)
{
    __shared__ __align__(16) float4 xs[DEPTH][2 * NT];           // 32 KB ring
    __shared__ __align__(16) unsigned long long ws2t[C_ * D_];   // 8 KB, [c][d]

    const int tid = threadIdx.x;
    const int bid = blockIdx.x;
    const int tchunk = bid & 1;
    const int i      = (bid >> 1) & (I_ - 1);
    const int b      = bid >> 5;

    const int t0 = tchunk * 1024 + tid * 8;
    const float* xg = x + (size_t)(b * I_ + i) * C_ * T_ + t0;

    // Thread's 32-byte slot within each stage.
    const uint32_t xs_base =
        (uint32_t)__cvta_generic_to_shared(&xs[0][0]) + (uint32_t)tid * 32u;
    const uint32_t STAGE = 2u * NT * 16u;   // bytes per stage

    // Warm up the pipeline (one commit group per stage: two 16B copies).
    #pragma unroll
    for (int s = 0; s < DEPTH; s++) {
        cp_async16(xs_base + (uint32_t)s * STAGE,      xg + (size_t)s * T_);
        cp_async16(xs_base + (uint32_t)s * STAGE + 16, xg + (size_t)s * T_ + 4);
        cp_commit();
    }

    // Renorm this i's weights in the warmup shadow. 4 warps, warp wid owns
    // rows d = 2*wid and 2*wid+1; writes transposed duplicated (w,w) pairs.
    {
        const int wid = tid >> 5, lane = tid & 31;
        #pragma unroll
        for (int r = 0; r < 2; r++) {
            const int d = 2 * wid + r;
            const float* wr = w + (i * D_ + d) * C_;
            float v0 = wr[lane], v1 = wr[lane + 32],
                  v2 = wr[lane + 64], v3 = wr[lane + 96];
            float s = v0 * v0 + v1 * v1 + v2 * v2 + v3 * v3;
            #pragma unroll
            for (int off = 16; off > 0; off >>= 1)
                s += __shfl_xor_sync(0xffffffffu, s, off);
            float n = sqrtf(s);
            float sc = (n > 1.0f) ? (1.0f / n) : 1.0f;
            v0 *= sc; v1 *= sc; v2 *= sc; v3 *= sc;
            ws2t[(lane      ) * D_ + d] = pack2(v0, v0);
            ws2t[(lane + 32 ) * D_ + d] = pack2(v1, v1);
            ws2t[(lane + 64 ) * D_ + d] = pack2(v2, v2);
            ws2t[(lane + 96 ) * D_ + d] = pack2(v3, v3);
        }
    }
    __syncthreads();

    // Accumulators: 8 d x 8 t = 64 fp32 as 32 packed u64.
    unsigned long long acc[D_][4];
    #pragma unroll
    for (int d = 0; d < D_; d++)
        #pragma unroll
        for (int q = 0; q < 4; q++) acc[d][q] = 0ull;

    const float* xg_pf = xg + (size_t)DEPTH * T_;

    #pragma unroll 4
    for (int c = 0; c < C_; c++) {
        cp_wait<DEPTH - 1>();   // stage c landed

        const int slot = c & (DEPTH - 1);
        float4 xa = xs[slot][2 * tid];
        float4 xb = xs[slot][2 * tid + 1];
        unsigned long long x0 = pack2(xa.x, xa.y);
        unsigned long long x1 = pack2(xa.z, xa.w);
        unsigned long long x2 = pack2(xb.x, xb.y);
        unsigned long long x3 = pack2(xb.z, xb.w);

        #pragma unroll
        for (int d = 0; d < D_; d++) {
            unsigned long long wv = ws2t[c * D_ + d];  // broadcast LDS.64
            acc[d][0] = fma2(x0, wv, acc[d][0]);
            acc[d][1] = fma2(x1, wv, acc[d][1]);
            acc[d][2] = fma2(x2, wv, acc[d][2]);
            acc[d][3] = fma2(x3, wv, acc[d][3]);
        }

        // Refill the consumed slot (thread-private: no barrier needed).
        if (c < C_ - DEPTH) {
            const uint32_t sa = xs_base + (uint32_t)slot * STAGE;
            cp_async16(sa,      xg_pf + (size_t)c * T_);
            cp_async16(sa + 16, xg_pf + (size_t)c * T_ + 4);
        }
        cp_commit();   // one (possibly empty) group per iter for accounting
    }

    float4* __restrict__ op = reinterpret_cast<float4*>(
        out + (size_t)(b * (I_ * D_) + i * D_) * T_ + t0);
    #pragma unroll
    for (int d = 0; d < D_; d++) {
        float4 oa, ob;
        unpack2(acc[d][0], oa.x, oa.y);
        unpack2(acc[d][1], oa.z, oa.w);
        unpack2(acc[d][2], ob.x, ob.y);
        unpack2(acc[d][3], ob.z, ob.w);
        op[(size_t)d * (T_ / 4)]     = oa;
        op[(size_t)d * (T_ / 4) + 1] = ob;
    }
}

extern "C" void kernel_launch(void* const* d_in, const int* in_sizes, int n_in,
                              void* d_out, int out_size) {
    const float* x = (const float*)d_in[0];   // (32,16,128,2048) fp32
    const float* w = (const float*)d_in[1];   // (256,1,128,1)    fp32
    float* out = (float*)d_out;               // (32,256,1,2048)  fp32
    (void)in_sizes; (void)n_in; (void)out_size;

    dwconv_kernel<<<B_ * I_ * (T_ / 1024), NT>>>(x, w, out);
}